// round 9
// baseline (speedup 1.0000x reference)
#include <cuda_runtime.h>
#include <cuda_bf16.h>

// Problem constants
#define BATCH 4
#define SEQ   4096
#define DM    1024
#define NH    16
#define EP    256
#define HDIM  64
#define MROWS (BATCH*SEQ)     // 16384
#define KA    2048            // split-K columns: [hi | lo]
#define NC    3072            // q|k|v output columns

// ---------------------------------------------------------------------------
// Scratch (static __device__ arrays — allocation APIs are forbidden)
// ---------------------------------------------------------------------------
__device__ unsigned short g_A [(size_t)MROWS * KA];        // x hi|lo bf16
__device__ unsigned short g_Bt[(size_t)NC * KA];           // [Wq|Wk|Wv]^T hi|lo
__device__ float          g_q [(size_t)MROWS * DM];        // q fp32
__device__ unsigned short g_kth[(size_t)BATCH * DM * SEQ]; // k^T hi [b][d][n]
__device__ unsigned short g_ktl[(size_t)BATCH * DM * SEQ];
__device__ unsigned short g_vth[(size_t)BATCH * DM * SEQ];
__device__ unsigned short g_vtl[(size_t)BATCH * DM * SEQ];
__device__ unsigned short g_Pth[(size_t)EP * SEQ];         // P^T hi [e][n]
__device__ unsigned short g_Ptl[(size_t)EP * SEQ];
__device__ float          g_kp[(size_t)BATCH * EP * DM];   // k_proj [b][e][d]
__device__ float          g_vp[(size_t)BATCH * EP * DM];

// ---------------------------------------------------------------------------
// Baseline-PTX helpers: cp.async, ldmatrix, mma.sync (no 'a'-target features)
// ---------------------------------------------------------------------------
__device__ __forceinline__ unsigned smem_to_u32(const void* p) {
    unsigned a;
    asm("{ .reg .u64 t; cvta.to.shared.u64 t, %1; cvt.u32.u64 %0, t; }"
        : "=r"(a) : "l"(p));
    return a;
}
__device__ __forceinline__ void cp_async16(unsigned saddr, const void* g) {
    asm volatile("cp.async.cg.shared.global [%0], [%1], 16;"
                 :: "r"(saddr), "l"(g) : "memory");
}
#define CP_COMMIT() asm volatile("cp.async.commit_group;" ::: "memory")
#define CP_WAIT1()  asm volatile("cp.async.wait_group 1;" ::: "memory")

__device__ __forceinline__ void ldm_x4(unsigned& r0, unsigned& r1,
                                       unsigned& r2, unsigned& r3, unsigned a) {
    asm volatile("ldmatrix.sync.aligned.m8n8.x4.shared.b16 {%0,%1,%2,%3}, [%4];"
                 : "=r"(r0), "=r"(r1), "=r"(r2), "=r"(r3) : "r"(a));
}
__device__ __forceinline__ void mma16816(float* c, const unsigned* a,
                                         const unsigned* b) {
    asm volatile(
        "mma.sync.aligned.m16n8k16.row.col.f32.bf16.bf16.f32 "
        "{%0,%1,%2,%3}, {%4,%5,%6,%7}, {%8,%9}, {%0,%1,%2,%3};"
        : "+f"(c[0]), "+f"(c[1]), "+f"(c[2]), "+f"(c[3])
        : "r"(a[0]), "r"(a[1]), "r"(a[2]), "r"(a[3]), "r"(b[0]), "r"(b[1]));
}

// Swizzled 16B-chunk offset inside a [rows][32 bf16] tile (64 B/row)
__device__ __forceinline__ unsigned tile_off(int row, int c) {
    return (unsigned)(row * 64 + ((c ^ ((row >> 1) & 3)) << 4));
}

// fp32 -> bf16 hi/lo split
__device__ __forceinline__ void split_bf16(float v, unsigned short& h, unsigned short& l) {
    __nv_bfloat16 hb = __float2bfloat16(v);
    __nv_bfloat16 lb = __float2bfloat16(v - __bfloat162float(hb));
    h = __bfloat16_as_ushort(hb);
    l = __bfloat16_as_ushort(lb);
}

// ---------------------------------------------------------------------------
// Conversion kernels
// ---------------------------------------------------------------------------
__global__ __launch_bounds__(256) void conv_x(const float* __restrict__ x,
                                              unsigned short* __restrict__ A) {
    size_t i = ((size_t)blockIdx.x * 256 + threadIdx.x) * 4;
    float4 v = *(const float4*)(x + i);
    size_t row = i >> 10, c = i & 1023;
    unsigned short h[4], l[4];
    split_bf16(v.x, h[0], l[0]); split_bf16(v.y, h[1], l[1]);
    split_bf16(v.z, h[2], l[2]); split_bf16(v.w, h[3], l[3]);
    *(uint2*)(A + row * KA + c)        = *(uint2*)h;
    *(uint2*)(A + row * KA + 1024 + c) = *(uint2*)l;
}

__global__ __launch_bounds__(256) void conv_w(const float* __restrict__ Wq,
                                              const float* __restrict__ Wk,
                                              const float* __restrict__ Wv,
                                              unsigned short* __restrict__ Bt) {
    size_t i = (size_t)blockIdx.x * 256 + threadIdx.x;
    int z = (int)(i >> 20);
    int rem = (int)(i & 1048575);
    int k = rem >> 10, n = rem & 1023;
    const float* W = (z == 0) ? Wq : (z == 1) ? Wk : Wv;
    unsigned short h, l;
    split_bf16(W[(size_t)k * 1024 + n], h, l);
    size_t r = (size_t)(z * 1024 + n) * KA;
    Bt[r + k] = h;
    Bt[r + 1024 + k] = l;
}

__global__ __launch_bounds__(256) void conv_p(const float* __restrict__ P,
                                              unsigned short* __restrict__ Ph,
                                              unsigned short* __restrict__ Pl) {
    size_t i = (size_t)blockIdx.x * 256 + threadIdx.x;
    int n = (int)(i >> 8), e = (int)(i & 255);
    unsigned short h, l;
    split_bf16(P[i], h, l);
    Ph[(size_t)e * SEQ + n] = h;
    Pl[(size_t)e * SEQ + n] = l;
}

// ---------------------------------------------------------------------------
// GEMM mainloop: C[128,128] over 3 compensation passes, k-chunk 32,
// 3-stage cp.async pipeline (16KB/stage), 8 warps (2Mx4N), warp tile 64x32.
// ---------------------------------------------------------------------------
template<int KP32>
__device__ __forceinline__ void gemm_mainloop(
    const unsigned short* __restrict__ Ah, const unsigned short* __restrict__ Al,
    const unsigned short* __restrict__ Bh, const unsigned short* __restrict__ Bl,
    size_t lda, size_t ldb, unsigned sbase, float acc[4][4][4])
{
    const int tid = threadIdx.x;
    const int wid = tid >> 5, l = tid & 31;
    const int wm = wid & 1, wn = wid >> 1;
    constexpr int T = 3 * KP32;

    auto prefetch = [&](int t) {
        int buf = t % 3;
        int p   = t / KP32;
        int kt  = t % KP32;
        int koff = kt * 32;
        const unsigned short* sA = (p == 1) ? Al : Ah;
        const unsigned short* sB = (p == 2) ? Bl : Bh;
        unsigned abase = sbase + buf * 16384;
        unsigned bbase = abase + 8192;
#pragma unroll
        for (int j = 0; j < 2; j++) {
            int i = tid + j * 256;
            int row = i >> 2, c = i & 3;
            unsigned so = tile_off(row, c);
            cp_async16(abase + so, sA + (size_t)row * lda + koff + c * 8);
            cp_async16(bbase + so, sB + (size_t)row * ldb + koff + c * 8);
        }
    };

    prefetch(0); CP_COMMIT();
    prefetch(1); CP_COMMIT();
    for (int t = 0; t < T; t++) {
        CP_WAIT1();                 // stage t landed (t+1 may be in flight)
        __syncthreads();            // all warps done with buffer (t+2)%3 too
        if (t + 2 < T) { prefetch(t + 2); CP_COMMIT(); }
        unsigned abase = sbase + (t % 3) * 16384;
        unsigned bbase = abase + 8192;
#pragma unroll
        for (int s = 0; s < 2; s++) {
            unsigned af[4][4], bf[4][2];
#pragma unroll
            for (int tm = 0; tm < 4; tm++) {
                int row = wm * 64 + tm * 16 + (l & 15);
                int c   = 2 * s + (l >> 4);
                ldm_x4(af[tm][0], af[tm][1], af[tm][2], af[tm][3],
                       abase + tile_off(row, c));
            }
#pragma unroll
            for (int t2 = 0; t2 < 2; t2++) {
                int mi  = l >> 3;
                int row = wn * 32 + t2 * 16 + ((mi >> 1) << 3) + (l & 7);
                int c   = 2 * s + (mi & 1);
                ldm_x4(bf[2 * t2][0], bf[2 * t2][1], bf[2 * t2 + 1][0], bf[2 * t2 + 1][1],
                       bbase + tile_off(row, c));
            }
#pragma unroll
            for (int tm = 0; tm < 4; tm++)
#pragma unroll
                for (int tn = 0; tn < 4; tn++)
                    mma16816(acc[tm][tn], af[tm], bf[tn]);
        }
    }
}

// Stage one 64-col half of the accumulators into Cs[128][65]
__device__ __forceinline__ void stage_acc_half(float* Cs, float acc[4][4][4],
                                               int wid, int l, int h) {
    const int wm = wid & 1, wn = wid >> 1;
    if ((wn >> 1) != h) return;          // only 4 warps own this half
    const int wn2 = wn & 1;
#pragma unroll
    for (int tm = 0; tm < 4; tm++)
#pragma unroll
        for (int tn = 0; tn < 4; tn++) {
            int r  = wm * 64 + tm * 16 + (l >> 2);
            int cc = wn2 * 32 + tn * 8 + (l & 3) * 2;
            Cs[r * 65 + cc]           = acc[tm][tn][0];
            Cs[r * 65 + cc + 1]       = acc[tm][tn][1];
            Cs[(r + 8) * 65 + cc]     = acc[tm][tn][2];
            Cs[(r + 8) * 65 + cc + 1] = acc[tm][tn][3];
        }
}

#define GEMM_SMEM 49152   // 3 stages x 16KB; epilogue reuses (needs 33.3KB)

// ---------------------------------------------------------------------------
// QKV GEMM: C[16384, 3072], tiles 128x128 -> grid (24, 128).
// Epilogue (two 64-col halves): q fp32 direct; k/v transposed hi/lo bf16.
// ---------------------------------------------------------------------------
__global__ __launch_bounds__(256, 2) void gemm_qkv(
    const unsigned short* __restrict__ A, const unsigned short* __restrict__ Bt,
    float* __restrict__ outq,
    unsigned short* __restrict__ kth, unsigned short* __restrict__ ktl,
    unsigned short* __restrict__ vth, unsigned short* __restrict__ vtl)
{
    extern __shared__ char smem[];
    unsigned sbase = smem_to_u32(smem);
    const int tid = threadIdx.x, wid = tid >> 5, l = tid & 31;
    const int m0 = blockIdx.y * 128;
    const int c0 = blockIdx.x * 128;

    float acc[4][4][4];
#pragma unroll
    for (int i = 0; i < 4; i++)
#pragma unroll
        for (int j = 0; j < 4; j++)
#pragma unroll
            for (int k = 0; k < 4; k++) acc[i][j][k] = 0.f;

    const unsigned short* Abase = A + (size_t)m0 * KA;
    const unsigned short* Bbase = Bt + (size_t)c0 * KA;
    gemm_mainloop<32>(Abase, Abase + 1024, Bbase, Bbase + 1024, KA, KA, sbase, acc);

    float* Cs = (float*)smem;
    const int mtx = c0 >> 10;       // 0=q, 1=k, 2=v
    const int cw  = c0 & 1023;
    const int b = m0 >> 12, nb = m0 & 4095;

#pragma unroll
    for (int h = 0; h < 2; h++) {
        __syncthreads();
        stage_acc_half(Cs, acc, wid, l, h);
        __syncthreads();
        if (mtx == 0) {
            for (int i = tid; i < 8192; i += 256) {
                int r = i >> 6, c = i & 63;
                outq[(size_t)(m0 + r) * DM + cw + h * 64 + c] = Cs[r * 65 + c];
            }
        } else {
            unsigned short* dh = (mtx == 1) ? kth : vth;
            unsigned short* dl = (mtx == 1) ? ktl : vtl;
            for (int i = tid; i < 8192; i += 256) {
                int r = i & 127, c = i >> 7;   // lanes consecutive in r(=n)
                unsigned short hh, lo;
                split_bf16(Cs[r * 65 + c], hh, lo);
                size_t a = ((size_t)b * DM + cw + h * 64 + c) * SEQ + nb + r;
                dh[a] = hh; dl[a] = lo;
            }
        }
    }
}

// ---------------------------------------------------------------------------
// Projection GEMM: per (b,{k,v}): C[d-tile, e-tile] = kt[b] @ Pt, K=4096 x3.
// grid (EP/128=2, DM/128=8, 8). Output kp/vp [b][e][d] (transposed write).
// ---------------------------------------------------------------------------
__global__ __launch_bounds__(256, 2) void gemm_proj(
    const unsigned short* __restrict__ kth, const unsigned short* __restrict__ ktl,
    const unsigned short* __restrict__ vth, const unsigned short* __restrict__ vtl,
    const unsigned short* __restrict__ Pth, const unsigned short* __restrict__ Ptl,
    float* __restrict__ kp, float* __restrict__ vp)
{
    extern __shared__ char smem[];
    unsigned sbase = smem_to_u32(smem);
    const int tid = threadIdx.x, wid = tid >> 5, l = tid & 31;
    const int e0 = blockIdx.x * 128;
    const int d0 = blockIdx.y * 128;
    const int z  = blockIdx.z;
    const int b  = z >> 1;
    const int mtx = z & 1;

    const unsigned short* Ah = (mtx ? vth : kth) + ((size_t)b * DM + d0) * SEQ;
    const unsigned short* Al = (mtx ? vtl : ktl) + ((size_t)b * DM + d0) * SEQ;
    const unsigned short* Bh = Pth + (size_t)e0 * SEQ;
    const unsigned short* Bl = Ptl + (size_t)e0 * SEQ;

    float acc[4][4][4];
#pragma unroll
    for (int i = 0; i < 4; i++)
#pragma unroll
        for (int j = 0; j < 4; j++)
#pragma unroll
            for (int k = 0; k < 4; k++) acc[i][j][k] = 0.f;

    gemm_mainloop<128>(Ah, Al, Bh, Bl, SEQ, SEQ, sbase, acc);

    float* Cs = (float*)smem;       // rows = d (M), cols = e (N)
    float* out = (mtx ? vp : kp) + (size_t)b * EP * DM;
#pragma unroll
    for (int h = 0; h < 2; h++) {
        __syncthreads();
        stage_acc_half(Cs, acc, wid, l, h);
        __syncthreads();
        for (int i = tid; i < 8192; i += 256) {
            int r = i & 127, c = i >> 7;   // lanes consecutive in r(=d)
            out[(size_t)(e0 + h * 64 + c) * DM + d0 + r] = Cs[r * 65 + c];
        }
    }
}

// ---------------------------------------------------------------------------
// Fused attention v2: 512 threads, thread-pair split of head dim.
// Each pair owns one query row; thread handles 32 of 64 dims (q + acc in
// regs ~80 total), dot completed via shfl_xor. K/V fp32 in 128KB smem.
// Grid: (SEQ/256, BATCH*NH).
// ---------------------------------------------------------------------------
__global__ __launch_bounds__(512) void attn_fused(
    const float* __restrict__ q, const float* __restrict__ kp,
    const float* __restrict__ vp, float* __restrict__ out)
{
    extern __shared__ float smemf[];
    float* Ks = smemf;               // [EP][HDIM]
    float* Vs = smemf + EP * HDIM;

    const int bh = blockIdx.y;
    const int b  = bh >> 4;
    const int h  = bh & 15;
    const int n0 = blockIdx.x * 256;

    const float* kpb = kp + (size_t)b * EP * DM + h * HDIM;
    const float* vpb = vp + (size_t)b * EP * DM + h * HDIM;

    for (int i = threadIdx.x; i < EP * HDIM / 4; i += 512) {
        int e = i >> 4, d4 = (i & 15) << 2;
        ((float4*)Ks)[i] = *(const float4*)(kpb + (size_t)e * DM + d4);
        ((float4*)Vs)[i] = *(const float4*)(vpb + (size_t)e * DM + d4);
    }
    __syncthreads();

    const int pair = threadIdx.x >> 1;     // 0..255 : row within chunk
    const int half = threadIdx.x & 1;      // which 32 dims
    const int n = n0 + pair;
    const int doff = half * 32;

    const float4* qrow = (const float4*)(q + (size_t)(b * SEQ + n) * DM + h * HDIM + doff);
    float4 qr[8];
#pragma unroll
    for (int i = 0; i < 8; i++) qr[i] = qrow[i];

    float4 acc[8];
#pragma unroll
    for (int i = 0; i < 8; i++) acc[i] = make_float4(0.f, 0.f, 0.f, 0.f);

    float m = -1e30f, lsum = 0.f;

    for (int e = 0; e < EP; e++) {
        const float4* kr = (const float4*)(Ks + e * HDIM + doff);
        float s0 = 0.f, s1 = 0.f, s2 = 0.f, s3 = 0.f;
#pragma unroll
        for (int i = 0; i < 8; i++) {
            float4 kv = kr[i];
            s0 += qr[i].x * kv.x; s1 += qr[i].y * kv.y;
            s2 += qr[i].z * kv.z; s3 += qr[i].w * kv.w;
        }
        float sh = (s0 + s1) + (s2 + s3);
        float s = (sh + __shfl_xor_sync(0xffffffffu, sh, 1)) * 0.125f;

        if (s > m) {
            float c = __expf(m - s);
            lsum *= c;
#pragma unroll
            for (int i = 0; i < 8; i++) {
                acc[i].x *= c; acc[i].y *= c; acc[i].z *= c; acc[i].w *= c;
            }
            m = s;
        }
        float p = __expf(s - m);
        lsum += p;

        const float4* vr = (const float4*)(Vs + e * HDIM + doff);
#pragma unroll
        for (int i = 0; i < 8; i++) {
            float4 vv = vr[i];
            acc[i].x += p * vv.x; acc[i].y += p * vv.y;
            acc[i].z += p * vv.z; acc[i].w += p * vv.w;
        }
    }

    float inv = 1.f / lsum;
    float4* orow = (float4*)(out + (size_t)(b * SEQ + n) * DM + h * HDIM + doff);
#pragma unroll
    for (int i = 0; i < 8; i++)
        orow[i] = make_float4(acc[i].x * inv, acc[i].y * inv,
                              acc[i].z * inv, acc[i].w * inv);
}

// ---------------------------------------------------------------------------
// Launch
// ---------------------------------------------------------------------------
extern "C" void kernel_launch(void* const* d_in, const int* in_sizes, int n_in,
                              void* d_out, int out_size)
{
    const float* x  = (const float*)d_in[0];
    const float* P  = (const float*)d_in[1];
    const float* Wq = (const float*)d_in[2];
    const float* Wk = (const float*)d_in[3];
    const float* Wv = (const float*)d_in[4];
    float* out = (float*)d_out;

    void *pA, *pBt, *pq, *pkth, *pktl, *pvth, *pvtl, *pPth, *pPtl, *pkp, *pvp;
    cudaGetSymbolAddress(&pA,   g_A);
    cudaGetSymbolAddress(&pBt,  g_Bt);
    cudaGetSymbolAddress(&pq,   g_q);
    cudaGetSymbolAddress(&pkth, g_kth);
    cudaGetSymbolAddress(&pktl, g_ktl);
    cudaGetSymbolAddress(&pvth, g_vth);
    cudaGetSymbolAddress(&pvtl, g_vtl);
    cudaGetSymbolAddress(&pPth, g_Pth);
    cudaGetSymbolAddress(&pPtl, g_Ptl);
    cudaGetSymbolAddress(&pkp,  g_kp);
    cudaGetSymbolAddress(&pvp,  g_vp);

    cudaFuncSetAttribute(gemm_qkv,  cudaFuncAttributeMaxDynamicSharedMemorySize, GEMM_SMEM);
    cudaFuncSetAttribute(gemm_proj, cudaFuncAttributeMaxDynamicSharedMemorySize, GEMM_SMEM);
    cudaFuncSetAttribute(attn_fused, cudaFuncAttributeMaxDynamicSharedMemorySize,
                         2 * EP * HDIM * (int)sizeof(float));

    // 1) hi/lo bf16 splits
    conv_x<<<(MROWS * DM) / (256 * 4), 256>>>(x, (unsigned short*)pA);
    conv_w<<<(3 * DM * DM) / 256, 256>>>(Wq, Wk, Wv, (unsigned short*)pBt);
    conv_p<<<(SEQ * EP) / 256, 256>>>(P, (unsigned short*)pPth, (unsigned short*)pPtl);

    // 2) QKV GEMM: grid (24, 128)
    gemm_qkv<<<dim3(NC / 128, MROWS / 128), 256, GEMM_SMEM>>>(
        (const unsigned short*)pA, (const unsigned short*)pBt,
        (float*)pq,
        (unsigned short*)pkth, (unsigned short*)pktl,
        (unsigned short*)pvth, (unsigned short*)pvtl);

    // 3) low-rank projection GEMMs: grid (2, 8, 8)
    gemm_proj<<<dim3(EP / 128, DM / 128, 2 * BATCH), 256, GEMM_SMEM>>>(
        (const unsigned short*)pkth, (const unsigned short*)pktl,
        (const unsigned short*)pvth, (const unsigned short*)pvtl,
        (const unsigned short*)pPth, (const unsigned short*)pPtl,
        (float*)pkp, (float*)pvp);

    // 4) fused attention: grid (16, 64), 512 threads
    attn_fused<<<dim3(SEQ / 256, BATCH * NH), 512,
                 2 * EP * HDIM * (int)sizeof(float)>>>(
        (const float*)pq, (const float*)pkp, (const float*)pvp, out);
}